// round 4
// baseline (speedup 1.0000x reference)
#include <cuda_runtime.h>

#define NN   50000
#define EMB  128
#define HC   192      // HEADS*HID = 3*64
#define NE   800000

#define GEMM_BX 391                    // ceil(50000/128)
#define GEMM_BLOCKS (GEMM_BX * 3 * 2)  // bx * head * {xl,xr}
#define HIST_BLOCKS ((NE + 255) / 256)

// ---------------- scratch ---------------------------------------------------
__device__ float g_xl[(size_t)NN * HC];
__device__ float g_xr[(size_t)NN * HC];
__device__ float g_u[NN * 4];        // att . xl_row  per head (pad 4)
__device__ float g_v[NN * 4];        // att . xr_row  per head
__device__ float g_kh[4];            // att . We per head
__device__ float g_cb[4];            // att.(bl+br) per head
__device__ int   g_cnt[NN];
__device__ int   g_off[NN];
__device__ int2  g_edge[NE];
__device__ float g_scores[NN];

// ---------------- tf32 helpers ----------------------------------------------
__device__ __forceinline__ unsigned f2tf(float x) {
    unsigned r;
    asm("cvt.rna.tf32.f32 %0, %1;" : "=r"(r) : "f"(x));
    return r;
}
__device__ __forceinline__ float2 split_tf32(float v) {
    unsigned hi = f2tf(v);
    float hf = __uint_as_float(hi);
    unsigned lo = f2tf(v - hf);
    return make_float2(hf, __uint_as_float(lo));
}
#define MMA_TF32(d, a0, a1, a2, a3, b0, b1)                                   \
    asm volatile(                                                              \
        "mma.sync.aligned.m16n8k8.row.col.f32.tf32.tf32.f32 "                  \
        "{%0,%1,%2,%3}, {%4,%5,%6,%7}, {%8,%9}, {%0,%1,%2,%3};"                \
        : "+f"(d[0]), "+f"(d[1]), "+f"(d[2]), "+f"(d[3])                       \
        : "r"(a0), "r"(a1), "r"(a2), "r"(a3), "r"(b0), "r"(b1))

// ---------------- 3xTF32 GEMM (xl & xr) + fused histogram -------------------
// block tile 128x64 (one head per by), 8 warps (4 along M, 2 along N),
// warp tile 32x32 = 2 m-frags x 4 n-frags of m16n8k8; k-chunks of 16.
__global__ void __launch_bounds__(256) k_gemm_hist(
    const float* __restrict__ A,
    const float* __restrict__ Wl, const float* __restrict__ bl,
    const float* __restrict__ Wr, const float* __restrict__ br,
    const float* __restrict__ att,
    const int*   __restrict__ ei)
{
    int bid = blockIdx.x;
    if (bid >= GEMM_BLOCKS) {
        int e = (bid - GEMM_BLOCKS) * 256 + threadIdx.x;
        if (e < NE) atomicAdd(&g_cnt[ei[NE + e]], 1);
        return;
    }

    int bz = bid / (GEMM_BX * 3);
    int r_ = bid % (GEMM_BX * 3);
    int by = r_ / GEMM_BX;             // head
    int bx = r_ % GEMM_BX;

    const float* W    = bz ? Wr : Wl;
    const float* bias = bz ? br : bl;
    float*       out  = bz ? g_xr : g_xl;
    float*       uv   = bz ? g_v  : g_u;

    __shared__ float2 A_s[16 * 133];   // [k][row], pitch 133 (bank-safe)
    __shared__ float2 B_s[16 * 69];    // [k][col], pitch 69

    int row0 = bx * 128;
    int col0 = by * 64;
    int tid  = threadIdx.x;
    int lane = tid & 31;
    int w    = tid >> 5;
    int mw   = (w >> 1) * 32;
    int nw   = (w & 1) * 32;
    int lr4  = lane >> 2;              // 0..7
    int lc4  = lane & 3;               // 0..3

    float acc[2][4][4];
    #pragma unroll
    for (int mf = 0; mf < 2; mf++)
        #pragma unroll
        for (int nf = 0; nf < 4; nf++)
            #pragma unroll
            for (int q = 0; q < 4; q++) acc[mf][nf][q] = 0.f;

    for (int k0 = 0; k0 < EMB; k0 += 16) {
        // A tile: 128 rows x 16 k
        #pragma unroll
        for (int q = 0; q < 2; q++) {
            int idx = q * 256 + tid;
            int row = idx >> 2;
            int kq  = (idx & 3) << 2;
            float4 a4 = make_float4(0.f, 0.f, 0.f, 0.f);
            int gr = row0 + row;
            if (gr < NN) a4 = *(const float4*)&A[(size_t)gr * EMB + k0 + kq];
            A_s[(kq + 0) * 133 + row] = split_tf32(a4.x);
            A_s[(kq + 1) * 133 + row] = split_tf32(a4.y);
            A_s[(kq + 2) * 133 + row] = split_tf32(a4.z);
            A_s[(kq + 3) * 133 + row] = split_tf32(a4.w);
        }
        // B tile: 64 cols x 16 k
        {
            int col = tid >> 2;
            int kq  = (tid & 3) << 2;
            float4 b4 = *(const float4*)&W[(size_t)(col0 + col) * EMB + k0 + kq];
            B_s[(kq + 0) * 69 + col] = split_tf32(b4.x);
            B_s[(kq + 1) * 69 + col] = split_tf32(b4.y);
            B_s[(kq + 2) * 69 + col] = split_tf32(b4.z);
            B_s[(kq + 3) * 69 + col] = split_tf32(b4.w);
        }
        __syncthreads();

        #pragma unroll
        for (int s = 0; s < 2; s++) {
            int kb = s * 8;
            unsigned ah[2][4], al[2][4], bh[4][2], blo[4][2];
            #pragma unroll
            for (int mf = 0; mf < 2; mf++) {
                int rr = mw + mf * 16 + lr4;
                float2 e0 = A_s[(kb + lc4) * 133 + rr];
                float2 e1 = A_s[(kb + lc4) * 133 + rr + 8];
                float2 e2 = A_s[(kb + lc4 + 4) * 133 + rr];
                float2 e3 = A_s[(kb + lc4 + 4) * 133 + rr + 8];
                ah[mf][0] = __float_as_uint(e0.x); al[mf][0] = __float_as_uint(e0.y);
                ah[mf][1] = __float_as_uint(e1.x); al[mf][1] = __float_as_uint(e1.y);
                ah[mf][2] = __float_as_uint(e2.x); al[mf][2] = __float_as_uint(e2.y);
                ah[mf][3] = __float_as_uint(e3.x); al[mf][3] = __float_as_uint(e3.y);
            }
            #pragma unroll
            for (int nf = 0; nf < 4; nf++) {
                int cc = nw + nf * 8 + lr4;
                float2 f0 = B_s[(kb + lc4) * 69 + cc];
                float2 f1 = B_s[(kb + lc4 + 4) * 69 + cc];
                bh[nf][0] = __float_as_uint(f0.x); blo[nf][0] = __float_as_uint(f0.y);
                bh[nf][1] = __float_as_uint(f1.x); blo[nf][1] = __float_as_uint(f1.y);
            }
            #pragma unroll
            for (int mf = 0; mf < 2; mf++)
                #pragma unroll
                for (int nf = 0; nf < 4; nf++) {
                    MMA_TF32(acc[mf][nf], al[mf][0], al[mf][1], al[mf][2], al[mf][3],
                             bh[nf][0], bh[nf][1]);
                    MMA_TF32(acc[mf][nf], ah[mf][0], ah[mf][1], ah[mf][2], ah[mf][3],
                             blo[nf][0], blo[nf][1]);
                    MMA_TF32(acc[mf][nf], ah[mf][0], ah[mf][1], ah[mf][2], ah[mf][3],
                             bh[nf][0], bh[nf][1]);
                }
        }
        __syncthreads();
    }

    // epilogue: write out (+bias) and accumulate u = att . row (pre-bias)
    float pu[4] = {0.f, 0.f, 0.f, 0.f};
    #pragma unroll
    for (int mf = 0; mf < 2; mf++) {
        int gr = row0 + mw + mf * 16 + lr4;
        #pragma unroll
        for (int nf = 0; nf < 4; nf++) {
            float* d = acc[mf][nf];
            int gc = col0 + nw + nf * 8 + 2 * lc4;
            float bb0 = __ldg(&bias[gc]), bb1 = __ldg(&bias[gc + 1]);
            float at0 = __ldg(&att[gc]),  at1 = __ldg(&att[gc + 1]);
            if (gr < NN)
                *(float2*)&out[(size_t)gr * HC + gc] = make_float2(d[0] + bb0, d[1] + bb1);
            if (gr + 8 < NN)
                *(float2*)&out[(size_t)(gr + 8) * HC + gc] = make_float2(d[2] + bb0, d[3] + bb1);
            pu[mf * 2 + 0] += d[0] * at0 + d[1] * at1;
            pu[mf * 2 + 1] += d[2] * at0 + d[3] * at1;
        }
    }
    #pragma unroll
    for (int q = 0; q < 4; q++) {
        float v = pu[q];
        v += __shfl_xor_sync(0xffffffffu, v, 1);
        v += __shfl_xor_sync(0xffffffffu, v, 2);
        if (lc4 == 0) {
            int gr = row0 + mw + (q >> 1) * 16 + lr4 + (q & 1) * 8;
            if (gr < NN) atomicAdd(&uv[gr * 4 + by], v);
        }
    }
}

// ---------------- scan (+ per-head constants) --------------------------------
__global__ void k_scan(const float* __restrict__ att, const float* __restrict__ We,
                       const float* __restrict__ bl,  const float* __restrict__ br) {
    __shared__ int wsum[32];
    __shared__ int carry;
    int tid  = threadIdx.x;
    int lane = tid & 31;
    int wid  = tid >> 5;

    if (tid < 96) {                     // warps 0..2, one head each
        int h = wid, c = h * 64 + lane;
        float p1 = att[c] * We[c] + att[c + 32] * We[c + 32];
        float p2 = att[c] * (bl[c] + br[c]) + att[c + 32] * (bl[c + 32] + br[c + 32]);
        #pragma unroll
        for (int o = 16; o > 0; o >>= 1) {
            p1 += __shfl_xor_sync(0xffffffffu, p1, o);
            p2 += __shfl_xor_sync(0xffffffffu, p2, o);
        }
        if (lane == 0) { g_kh[h] = p1; g_cb[h] = p2; }
    }

    if (tid == 0) carry = 0;
    __syncthreads();

    for (int base = 0; base < NN; base += 1024) {
        int i = base + tid;
        int v = (i < NN) ? g_cnt[i] : 0;
        int x = v;
        #pragma unroll
        for (int o = 1; o < 32; o <<= 1) {
            int t = __shfl_up_sync(0xffffffffu, x, o);
            if (lane >= o) x += t;
        }
        if (lane == 31) wsum[wid] = x;
        __syncthreads();
        if (wid == 0) {
            int s = wsum[lane];
            #pragma unroll
            for (int o = 1; o < 32; o <<= 1) {
                int t = __shfl_up_sync(0xffffffffu, s, o);
                if (lane >= o) s += t;
            }
            wsum[lane] = s;
        }
        __syncthreads();
        int c = carry;
        int exb = (wid > 0 ? wsum[wid - 1] : 0) + c;
        if (i < NN) g_off[i] = exb + x - v;
        __syncthreads();
        if (tid == 0) carry = c + wsum[31];
        __syncthreads();
    }
}

// ---------------- scatter ----------------------------------------------------
__global__ void k_scatter(const int* __restrict__ ei, const float* __restrict__ ea) {
    int e = blockIdx.x * blockDim.x + threadIdx.x;
    if (e >= NE) return;
    int s = ei[e];
    int d = ei[NE + e];
    int p = atomicAdd(&g_off[d], 1);
    g_edge[p] = make_int2(s, __float_as_int(ea[e]));
}

// ---------------- warp-per-node aggregation ---------------------------------
// leaky(m,.2) = 0.6m + 0.4|m| ; linear part via precomputed u/v/kh/cb.
__global__ void __launch_bounds__(128) k_agg(
    const float* __restrict__ We, const float* __restrict__ att,
    const float* __restrict__ bias, const float* __restrict__ Wout,
    const float* __restrict__ bout)
{
    int n = (blockIdx.x * blockDim.x + threadIdx.x) >> 5;
    int l = threadIdx.x & 31;
    if (n >= NN) return;

    int end = g_off[n];
    int beg = (n > 0) ? g_off[n - 1] : 0;

    const float LOG2E = 1.44269504088896f;
    const float C06 = 0.6f * LOG2E;
    const float C04 = 0.4f * LOG2E;

    float xi[6], aw[6], wv[6];
    #pragma unroll
    for (int j = 0; j < 6; j++) {
        int v = l + 32 * j;
        xi[j] = g_xr[(size_t)n * HC + v];
        aw[j] = att[v] * C04;
        wv[j] = We[v];
    }
    float vvc[3], kh06[3];
    #pragma unroll
    for (int h = 0; h < 3; h++) {
        vvc[h]  = g_v[n * 4 + h] + g_cb[h];
        kh06[h] = g_kh[h] * C06;
    }

    float rsum[3] = {0.f, 0.f, 0.f};
    float acc[6]  = {0.f, 0.f, 0.f, 0.f, 0.f, 0.f};

    int2 ed = (beg < end) ? g_edge[beg] : make_int2(0, 0);
    float4 u4 = *(const float4*)&g_u[ed.x * 4];
    float xj[6];
    #pragma unroll
    for (int j = 0; j < 6; j++) xj[j] = g_xl[(size_t)ed.x * HC + l + 32 * j];

    for (int i = beg; i < end; i++) {
        int2 ed2 = (i + 1 < end) ? g_edge[i + 1] : make_int2(0, 0);
        float4 u4n = *(const float4*)&g_u[ed2.x * 4];
        float xjn[6];
        #pragma unroll
        for (int j = 0; j < 6; j++) xjn[j] = g_xl[(size_t)ed2.x * HC + l + 32 * j];

        float fe = __int_as_float(ed.y);
        float s0 = 0.f, s1 = 0.f, s2 = 0.f;
        {
            float m;
            m = fmaf(fe, wv[0], xi[0]) + xj[0]; s0 = fmaf(fabsf(m), aw[0], s0);
            m = fmaf(fe, wv[1], xi[1]) + xj[1]; s0 = fmaf(fabsf(m), aw[1], s0);
            m = fmaf(fe, wv[2], xi[2]) + xj[2]; s1 = fmaf(fabsf(m), aw[2], s1);
            m = fmaf(fe, wv[3], xi[3]) + xj[3]; s1 = fmaf(fabsf(m), aw[3], s1);
            m = fmaf(fe, wv[4], xi[4]) + xj[4]; s2 = fmaf(fabsf(m), aw[4], s2);
            m = fmaf(fe, wv[5], xi[5]) + xj[5]; s2 = fmaf(fabsf(m), aw[5], s2);
        }
        #pragma unroll
        for (int o = 16; o > 0; o >>= 1) {
            s0 += __shfl_xor_sync(0xffffffffu, s0, o);
            s1 += __shfl_xor_sync(0xffffffffu, s1, o);
            s2 += __shfl_xor_sync(0xffffffffu, s2, o);
        }
        float w0 = exp2f(fmaf(fe, kh06[0], fmaf(u4.x + vvc[0], C06, s0)));
        float w1 = exp2f(fmaf(fe, kh06[1], fmaf(u4.y + vvc[1], C06, s1)));
        float w2 = exp2f(fmaf(fe, kh06[2], fmaf(u4.z + vvc[2], C06, s2)));
        rsum[0] += w0; rsum[1] += w1; rsum[2] += w2;
        acc[0] += w0 * xj[0]; acc[1] += w0 * xj[1];
        acc[2] += w1 * xj[2]; acc[3] += w1 * xj[3];
        acc[4] += w2 * xj[4]; acc[5] += w2 * xj[5];

        ed = ed2; u4 = u4n;
        #pragma unroll
        for (int j = 0; j < 6; j++) xj[j] = xjn[j];
    }

    float o0 = 0.f, o1 = 0.f;
    if (end > beg) {
        o0 = (acc[0] / rsum[0] + acc[2] / rsum[1] + acc[4] / rsum[2]) * (1.f / 3.f);
        o1 = (acc[1] / rsum[0] + acc[3] / rsum[1] + acc[5] / rsum[2]) * (1.f / 3.f);
    }
    o0 += bias[l];
    o1 += bias[l + 32];

    float sp = o0 * Wout[l] + o1 * Wout[l + 32];
    #pragma unroll
    for (int o = 16; o > 0; o >>= 1) sp += __shfl_xor_sync(0xffffffffu, sp, o);
    if (l == 0) g_scores[n] = sp + bout[0];
}

// ---------------- global softmax --------------------------------------------
__global__ void k_softmax(float* __restrict__ out) {
    __shared__ float redm[32];
    __shared__ float reds[32];
    int tid = threadIdx.x;

    float mx = -1e30f;
    for (int i = tid; i < NN; i += 1024) mx = fmaxf(mx, g_scores[i]);
    #pragma unroll
    for (int o = 16; o > 0; o >>= 1) mx = fmaxf(mx, __shfl_xor_sync(0xffffffffu, mx, o));
    if ((tid & 31) == 0) redm[tid >> 5] = mx;
    __syncthreads();
    if (tid < 32) {
        float v = redm[tid];
        #pragma unroll
        for (int o = 16; o > 0; o >>= 1) v = fmaxf(v, __shfl_xor_sync(0xffffffffu, v, o));
        redm[tid] = v;
    }
    __syncthreads();
    mx = redm[0];

    float sm = 0.f;
    for (int i = tid; i < NN; i += 1024) {
        float e = __expf(g_scores[i] - mx);
        out[i] = e;
        sm += e;
    }
    #pragma unroll
    for (int o = 16; o > 0; o >>= 1) sm += __shfl_xor_sync(0xffffffffu, sm, o);
    if ((tid & 31) == 0) reds[tid >> 5] = sm;
    __syncthreads();
    if (tid < 32) {
        float v = reds[tid];
        #pragma unroll
        for (int o = 16; o > 0; o >>= 1) v += __shfl_xor_sync(0xffffffffu, v, o);
        reds[tid] = v;
    }
    __syncthreads();
    float inv = 1.f / reds[0];

    for (int i = tid; i < NN; i += 1024) out[i] *= inv;
}

// ---------------- launch ----------------------------------------------------
extern "C" void kernel_launch(void* const* d_in, const int* in_sizes, int n_in,
                              void* d_out, int out_size)
{
    const int*   ei   = (const int*)  d_in[0];
    const float* ea   = (const float*)d_in[1];
    const float* pe   = (const float*)d_in[2];
    // d_in[3] = sim_w: softmax over one element == 1.0 -> unused
    const float* Wl   = (const float*)d_in[4];
    const float* bl   = (const float*)d_in[5];
    const float* Wr   = (const float*)d_in[6];
    const float* br   = (const float*)d_in[7];
    const float* We   = (const float*)d_in[8];
    const float* att  = (const float*)d_in[9];
    const float* bgn  = (const float*)d_in[10];
    const float* Wout = (const float*)d_in[11];
    const float* bout = (const float*)d_in[12];
    float* out = (float*)d_out;

    void* p = nullptr;
    cudaGetSymbolAddress(&p, g_cnt); cudaMemsetAsync(p, 0, NN * sizeof(int), 0);
    cudaGetSymbolAddress(&p, g_u);   cudaMemsetAsync(p, 0, NN * 4 * sizeof(float), 0);
    cudaGetSymbolAddress(&p, g_v);   cudaMemsetAsync(p, 0, NN * 4 * sizeof(float), 0);

    k_gemm_hist<<<GEMM_BLOCKS + HIST_BLOCKS, 256>>>(pe, Wl, bl, Wr, br, att, ei);
    k_scan<<<1, 1024>>>(att, We, bl, br);
    k_scatter<<<HIST_BLOCKS, 256>>>(ei, ea);
    k_agg<<<(NN * 32 + 127) / 128, 128>>>(We, att, bgn, Wout, bout);
    k_softmax<<<1, 1024>>>(out);
}

// round 5
// speedup vs baseline: 1.0989x; 1.0989x over previous
#include <cuda_runtime.h>

#define NN   50000
#define EMB  128
#define HC   192      // HEADS*HID = 3*64
#define NE   800000

#define GEMM_BX 391                    // ceil(50000/128)
#define GEMM_BLOCKS (GEMM_BX * 3 * 2)  // 2346
#define HIST_BLOCKS ((NE + 255) / 256) // 3125

// ---------------- scratch (device globals; no allocation allowed) ----------
__device__ float g_xl[(size_t)NN * HC];
__device__ float g_xr[(size_t)NN * HC];
__device__ int   g_cnt[NN];
__device__ int   g_off[NN];          // exclusive offsets; consumed to ends by scatter
__device__ int2  g_edge[NE];         // (src, fe-as-int) packed
__device__ float g_scores[NN];

// ---------------- fused GEMM (xl & xr) + dst histogram ---------------------
// tile 128x64, 8x4 microtile, K-step 16; global loads reg-double-buffered so
// next tile's LDG latency hides under the 512-FFMA compute phase.
__global__ void __launch_bounds__(256) k_gemm_hist(
    const float* __restrict__ A,
    const float* __restrict__ Wl, const float* __restrict__ bl,
    const float* __restrict__ Wr, const float* __restrict__ br,
    const int*   __restrict__ ei)
{
    int bid = blockIdx.x;
    if (bid >= GEMM_BLOCKS) {
        int e = (bid - GEMM_BLOCKS) * 256 + threadIdx.x;
        if (e < NE) atomicAdd(&g_cnt[ei[NE + e]], 1);
        return;
    }

    int bz = bid / (GEMM_BX * 3);
    int r  = bid % (GEMM_BX * 3);
    int by = r / GEMM_BX;
    int bx = r % GEMM_BX;

    const float* W    = bz ? Wr : Wl;
    const float* bias = bz ? br : bl;
    float*       out  = bz ? g_xr : g_xl;

    __shared__ float As[16][128];
    __shared__ float Bs[16][64];

    int row0 = bx * 128;
    int col0 = by * 64;
    int tid  = threadIdx.x;
    int tx   = tid & 15;       // 0..15 -> 4 cols
    int ty   = tid >> 4;       // 0..15 -> 8 rows

    // A-load lanes: idx = tid + q*256 -> row = idx>>2, kq = (idx&3)*4
    int arow0 = tid >> 2;
    int arow1 = (tid + 256) >> 2;
    int akq   = (tid & 3) << 2;
    // B-load lanes
    int bcol  = tid >> 2;
    int bkq   = (tid & 3) << 2;

    float acc[8][4];
    #pragma unroll
    for (int i = 0; i < 8; i++)
        #pragma unroll
        for (int j = 0; j < 4; j++) acc[i][j] = 0.f;

    float4 ra0, ra1, rb;
    {   // prologue: load k-tile 0 into regs
        ra0 = make_float4(0.f, 0.f, 0.f, 0.f);
        ra1 = make_float4(0.f, 0.f, 0.f, 0.f);
        int g0 = row0 + arow0, g1 = row0 + arow1;
        if (g0 < NN) ra0 = *(const float4*)&A[(size_t)g0 * EMB + akq];
        if (g1 < NN) ra1 = *(const float4*)&A[(size_t)g1 * EMB + akq];
        rb = *(const float4*)&W[(size_t)(col0 + bcol) * EMB + bkq];
    }

    for (int k0 = 0; k0 < EMB; k0 += 16) {
        // store current regs -> smem (transpose A)
        As[akq + 0][arow0] = ra0.x; As[akq + 1][arow0] = ra0.y;
        As[akq + 2][arow0] = ra0.z; As[akq + 3][arow0] = ra0.w;
        As[akq + 0][arow1] = ra1.x; As[akq + 1][arow1] = ra1.y;
        As[akq + 2][arow1] = ra1.z; As[akq + 3][arow1] = ra1.w;
        Bs[bkq + 0][bcol] = rb.x; Bs[bkq + 1][bcol] = rb.y;
        Bs[bkq + 2][bcol] = rb.z; Bs[bkq + 3][bcol] = rb.w;
        __syncthreads();

        // issue next tile's global loads early (consumed after compute+sync)
        if (k0 + 16 < EMB) {
            int kn = k0 + 16;
            ra0 = make_float4(0.f, 0.f, 0.f, 0.f);
            ra1 = make_float4(0.f, 0.f, 0.f, 0.f);
            int g0 = row0 + arow0, g1 = row0 + arow1;
            if (g0 < NN) ra0 = *(const float4*)&A[(size_t)g0 * EMB + kn + akq];
            if (g1 < NN) ra1 = *(const float4*)&A[(size_t)g1 * EMB + kn + akq];
            rb = *(const float4*)&W[(size_t)(col0 + bcol) * EMB + kn + bkq];
        }

        #pragma unroll
        for (int kk = 0; kk < 16; kk++) {
            float4 a0 = *(const float4*)&As[kk][ty * 8];
            float4 a1 = *(const float4*)&As[kk][ty * 8 + 4];
            float4 b  = *(const float4*)&Bs[kk][tx * 4];
            float av[8] = {a0.x, a0.y, a0.z, a0.w, a1.x, a1.y, a1.z, a1.w};
            float bv[4] = {b.x, b.y, b.z, b.w};
            #pragma unroll
            for (int i = 0; i < 8; i++)
                #pragma unroll
                for (int j = 0; j < 4; j++) acc[i][j] += av[i] * bv[j];
        }
        __syncthreads();
    }

    float4 bb = *(const float4*)&bias[col0 + tx * 4];
    #pragma unroll
    for (int i = 0; i < 8; i++) {
        int rr = row0 + ty * 8 + i;
        if (rr < NN) {
            float4 v = make_float4(acc[i][0] + bb.x, acc[i][1] + bb.y,
                                   acc[i][2] + bb.z, acc[i][3] + bb.w);
            *(float4*)&out[(size_t)rr * HC + col0 + tx * 4] = v;
        }
    }
}

// ---------------- warp-shuffle exclusive scan (single block) ---------------
__global__ void k_scan() {
    __shared__ int wsum[32];
    __shared__ int carry;
    int tid  = threadIdx.x;
    int lane = tid & 31;
    int wid  = tid >> 5;
    if (tid == 0) carry = 0;
    __syncthreads();

    for (int base = 0; base < NN; base += 1024) {
        int i = base + tid;
        int v = (i < NN) ? g_cnt[i] : 0;
        int x = v;
        #pragma unroll
        for (int o = 1; o < 32; o <<= 1) {
            int t = __shfl_up_sync(0xffffffffu, x, o);
            if (lane >= o) x += t;
        }
        if (lane == 31) wsum[wid] = x;
        __syncthreads();
        if (wid == 0) {
            int s = wsum[lane];
            #pragma unroll
            for (int o = 1; o < 32; o <<= 1) {
                int t = __shfl_up_sync(0xffffffffu, s, o);
                if (lane >= o) s += t;
            }
            wsum[lane] = s;
        }
        __syncthreads();
        int c = carry;
        int exb = (wid > 0 ? wsum[wid - 1] : 0) + c;
        if (i < NN) g_off[i] = exb + x - v;      // exclusive
        __syncthreads();
        if (tid == 0) carry = c + wsum[31];
        __syncthreads();
    }
}

// scatter: consumes g_off (after this, g_off[n] == end of bucket n)
__global__ void k_scatter(const int* __restrict__ ei, const float* __restrict__ ea) {
    int e = blockIdx.x * blockDim.x + threadIdx.x;
    if (e >= NE) return;
    int s = ei[e];
    int d = ei[NE + e];
    int p = atomicAdd(&g_off[d], 1);
    g_edge[p] = make_int2(s, __float_as_int(ea[e]));
}

// ---------------- warp-per-node GATv2 aggregation + output head ------------
// plain-sum softmax (shift-invariance; logits bounded for this data),
// att*leaky(m) = (0.6 att) m + (0.4 att)|m| -> 2 FMA per channel.
__global__ void __launch_bounds__(128) k_agg(
    const float* __restrict__ We, const float* __restrict__ att,
    const float* __restrict__ bias, const float* __restrict__ Wout,
    const float* __restrict__ bout)
{
    int n = (blockIdx.x * blockDim.x + threadIdx.x) >> 5;
    int l = threadIdx.x & 31;
    if (n >= NN) return;

    int end = g_off[n];
    int beg = (n > 0) ? g_off[n - 1] : 0;

    const float LOG2E = 1.44269504088896f;
    float xi[6], a06[6], a04[6], wv[6];
    #pragma unroll
    for (int j = 0; j < 6; j++) {
        int v = l + 32 * j;
        xi[j]  = g_xr[(size_t)n * HC + v];
        float a = att[v] * LOG2E;
        a06[j] = 0.6f * a;
        a04[j] = 0.4f * a;
        wv[j]  = We[v];
    }

    float rsum[3] = {0.f, 0.f, 0.f};
    float acc[6]  = {0.f, 0.f, 0.f, 0.f, 0.f, 0.f};

    int2 ed = (beg < end) ? g_edge[beg] : make_int2(0, 0);
    float xj[6];
    #pragma unroll
    for (int j = 0; j < 6; j++) xj[j] = g_xl[(size_t)ed.x * HC + l + 32 * j];

    for (int i = beg; i < end; i++) {
        int2 ed2 = (i + 1 < end) ? g_edge[i + 1] : make_int2(0, 0);
        float xjn[6];                              // speculative prefetch (s=0 safe)
        #pragma unroll
        for (int j = 0; j < 6; j++) xjn[j] = g_xl[(size_t)ed2.x * HC + l + 32 * j];

        float fe = __int_as_float(ed.y);
        float s0, s1, s2;
        {
            float m;
            m  = fmaf(fe, wv[0], xi[0]) + xj[0];
            s0 = fmaf(a06[0], m, a04[0] * fabsf(m));
            m  = fmaf(fe, wv[1], xi[1]) + xj[1];
            s0 = fmaf(a06[1], m, fmaf(a04[1], fabsf(m), s0));
            m  = fmaf(fe, wv[2], xi[2]) + xj[2];
            s1 = fmaf(a06[2], m, a04[2] * fabsf(m));
            m  = fmaf(fe, wv[3], xi[3]) + xj[3];
            s1 = fmaf(a06[3], m, fmaf(a04[3], fabsf(m), s1));
            m  = fmaf(fe, wv[4], xi[4]) + xj[4];
            s2 = fmaf(a06[4], m, a04[4] * fabsf(m));
            m  = fmaf(fe, wv[5], xi[5]) + xj[5];
            s2 = fmaf(a06[5], m, fmaf(a04[5], fabsf(m), s2));
        }
        #pragma unroll
        for (int o = 16; o > 0; o >>= 1) {
            s0 += __shfl_xor_sync(0xffffffffu, s0, o);
            s1 += __shfl_xor_sync(0xffffffffu, s1, o);
            s2 += __shfl_xor_sync(0xffffffffu, s2, o);
        }
        float w0 = exp2f(s0);
        float w1 = exp2f(s1);
        float w2 = exp2f(s2);
        rsum[0] += w0; rsum[1] += w1; rsum[2] += w2;
        acc[0] += w0 * xj[0]; acc[1] += w0 * xj[1];
        acc[2] += w1 * xj[2]; acc[3] += w1 * xj[3];
        acc[4] += w2 * xj[4]; acc[5] += w2 * xj[5];

        ed = ed2;
        #pragma unroll
        for (int j = 0; j < 6; j++) xj[j] = xjn[j];
    }

    float o0 = 0.f, o1 = 0.f;
    if (end > beg) {
        o0 = (acc[0] / rsum[0] + acc[2] / rsum[1] + acc[4] / rsum[2]) * (1.f / 3.f);
        o1 = (acc[1] / rsum[0] + acc[3] / rsum[1] + acc[5] / rsum[2]) * (1.f / 3.f);
    }
    o0 += bias[l];
    o1 += bias[l + 32];

    float sp = o0 * Wout[l] + o1 * Wout[l + 32];
    #pragma unroll
    for (int o = 16; o > 0; o >>= 1) sp += __shfl_xor_sync(0xffffffffu, sp, o);
    if (l == 0) g_scores[n] = sp + bout[0];
}

// ---------------- global softmax over 50k scores ---------------------------
__global__ void k_softmax(float* __restrict__ out) {
    __shared__ float redm[32];
    __shared__ float reds[32];
    int tid = threadIdx.x;

    float mx = -1e30f;
    for (int i = tid; i < NN; i += 1024) mx = fmaxf(mx, g_scores[i]);
    #pragma unroll
    for (int o = 16; o > 0; o >>= 1) mx = fmaxf(mx, __shfl_xor_sync(0xffffffffu, mx, o));
    if ((tid & 31) == 0) redm[tid >> 5] = mx;
    __syncthreads();
    if (tid < 32) {
        float v = redm[tid];
        #pragma unroll
        for (int o = 16; o > 0; o >>= 1) v = fmaxf(v, __shfl_xor_sync(0xffffffffu, v, o));
        redm[tid] = v;
    }
    __syncthreads();
    mx = redm[0];

    float sm = 0.f;
    for (int i = tid; i < NN; i += 1024) {
        float e = __expf(g_scores[i] - mx);
        out[i] = e;
        sm += e;
    }
    #pragma unroll
    for (int o = 16; o > 0; o >>= 1) sm += __shfl_xor_sync(0xffffffffu, sm, o);
    if ((tid & 31) == 0) reds[tid >> 5] = sm;
    __syncthreads();
    if (tid < 32) {
        float v = reds[tid];
        #pragma unroll
        for (int o = 16; o > 0; o >>= 1) v += __shfl_xor_sync(0xffffffffu, v, o);
        reds[tid] = v;
    }
    __syncthreads();
    float inv = 1.f / reds[0];

    for (int i = tid; i < NN; i += 1024) out[i] *= inv;
}

// ---------------- launch ----------------------------------------------------
extern "C" void kernel_launch(void* const* d_in, const int* in_sizes, int n_in,
                              void* d_out, int out_size)
{
    const int*   ei   = (const int*)  d_in[0];
    const float* ea   = (const float*)d_in[1];
    const float* pe   = (const float*)d_in[2];
    // d_in[3] = sim_w: softmax over one element == 1.0 -> unused
    const float* Wl   = (const float*)d_in[4];
    const float* bl   = (const float*)d_in[5];
    const float* Wr   = (const float*)d_in[6];
    const float* br   = (const float*)d_in[7];
    const float* We   = (const float*)d_in[8];
    const float* att  = (const float*)d_in[9];
    const float* bgn  = (const float*)d_in[10];
    const float* Wout = (const float*)d_in[11];
    const float* bout = (const float*)d_in[12];
    float* out = (float*)d_out;

    void* p_cnt = nullptr;
    cudaGetSymbolAddress(&p_cnt, g_cnt);
    cudaMemsetAsync(p_cnt, 0, NN * sizeof(int), 0);

    k_gemm_hist<<<GEMM_BLOCKS + HIST_BLOCKS, 256>>>(pe, Wl, bl, Wr, br, ei);
    k_scan<<<1, 1024>>>();
    k_scatter<<<HIST_BLOCKS, 256>>>(ei, ea);
    k_agg<<<(NN * 32 + 127) / 128, 128>>>(We, att, bgn, Wout, bout);
    k_softmax<<<1, 1024>>>(out);
}